// round 15
// baseline (speedup 1.0000x reference)
#include <cuda_runtime.h>
#include <cstdint>

#define F_DIM 128
#define PITCH 132
#define EPSV  1e-8f
#define LN2   0.6931471805599453f
#define RSQRT_F 0.08838834764831844f

#define N_CAP 524288
#define B_CAP 16384

__device__ float g_u [(size_t)B_CAP * F_DIM];
__device__ float g_vm[(size_t)B_CAP * F_DIM];
__device__ float g_d [B_CAP];
__device__ float g_anorm[B_CAP];
__device__ float g_w [N_CAP];
__device__ float g_max;
__device__ float g_Z;

__device__ __forceinline__ float sspf(float x) {
    float ax = fabsf(x);
    float l  = __logf(1.0f + __expf(-ax));
    return fmaxf(x, 0.0f) + (l - LN2);
}

__device__ __forceinline__ void atomicMaxFloat(float* addr, float v) {
    int* ai = (int*)addr;
    int cur = *ai;
    while (__int_as_float(cur) < v) {
        int prev = atomicCAS(ai, cur, __float_as_int(v));
        if (prev == cur) break;
        cur = prev;
    }
}

// ---- K0: per-molecule precompute: u = (Wq^T km)/sqrt(F), vm, d = km.bq/sqrt(F)
__global__ void k_prep(const float* __restrict__ ef, const float* __restrict__ Wk,
                       const float* __restrict__ Wv, const float* __restrict__ Wq,
                       const float* __restrict__ bq) {
    __shared__ float kms[128];
    __shared__ float red[128];
    const int b = blockIdx.x;
    const int f = threadIdx.x;
    if (b == 0 && f == 0) g_max = -1e30f;

    float e  = ef[b];
    float e0 = fmaxf(e, 0.0f), e1 = fmaxf(-e, 0.0f);
    float k0 = e0 / fmaxf(e0, 1.0f);
    float k1 = e1 / fmaxf(e1, 1.0f);
    float km = k0 * Wk[2 * f] + k1 * Wk[2 * f + 1];
    g_vm[(size_t)b * 128 + f] = e0 * Wv[2 * f] + e1 * Wv[2 * f + 1];
    kms[f] = km;
    red[f] = km * bq[f];
    __syncthreads();
    #pragma unroll
    for (int s = 64; s > 0; s >>= 1) {
        if (f < s) red[f] += red[f + s];
        __syncthreads();
    }
    if (f == 0) g_d[b] = red[0] * RSQRT_F;

    float acc = 0.0f;
    #pragma unroll 8
    for (int ff = 0; ff < 128; ff++)
        acc = fmaf(kms[ff], __ldg(&Wq[ff * 128 + f]), acc);
    g_u[(size_t)b * 128 + f] = acc * RSQRT_F;
}

// ---- K1: w[n] = u[idx].x_n + d[idx]; block max -> atomic max. 1 warp/atom.
__global__ void k_w(const float* __restrict__ X, const int* __restrict__ idx, int N) {
    __shared__ float smax[8];
    const int warp = threadIdx.x >> 5;
    const int lane = threadIdx.x & 31;
    const int row  = blockIdx.x * 8 + warp;
    float wv = -1e30f;
    if (row < N) {
        int b = __ldg(&idx[row]);
        float4 x = __ldg(&((const float4*)X)[(size_t)row * 32 + lane]);
        float4 u = ((const float4*)g_u)[(size_t)b * 32 + lane];
        float s = x.x * u.x + x.y * u.y + x.z * u.z + x.w * u.w;
        #pragma unroll
        for (int o = 16; o > 0; o >>= 1) s += __shfl_down_sync(0xffffffffu, s, o);
        if (lane == 0) {
            s += g_d[b];
            g_w[row] = s;
            wv = s;
        }
    }
    if (lane == 0) smax[warp] = wv;
    __syncthreads();
    if (threadIdx.x == 0) {
        float m = smax[0];
        #pragma unroll
        for (int i = 1; i < 8; i++) m = fmaxf(m, smax[i]);
        atomicMaxFloat(&g_max, m);
    }
}

// ---- K2: p = exp(w - max)
__global__ void k_exp(int N) {
    int n = blockIdx.x * blockDim.x + threadIdx.x;
    if (n < N) g_w[n] = expf(g_w[n] - g_max);
}

// ---- K3: deterministic per-molecule sums (binary search on sorted idx)
__global__ void k_anorm(const int* __restrict__ idx, int N, int B) {
    const int b = blockIdx.x * 8 + (threadIdx.x >> 5);
    const int lane = threadIdx.x & 31;
    if (b >= B) return;
    int lo = 0, hi = N;
    while (lo < hi) { int m = (lo + hi) >> 1; if (idx[m] < b) lo = m + 1; else hi = m; }
    const int s0 = lo;
    hi = N;
    while (lo < hi) { int m = (lo + hi) >> 1; if (idx[m] < b + 1) lo = m + 1; else hi = m; }
    const int e0 = lo;
    float sum = 0.0f;
    for (int n = s0 + lane; n < e0; n += 32) sum += g_w[n];
    #pragma unroll
    for (int o = 16; o > 0; o >>= 1) sum += __shfl_down_sync(0xffffffffu, sum, o);
    if (lane == 0) g_anorm[b] = sum;
}

// ---- K4: Z = sum anorm (single block, fixed order)
__global__ void k_Z(int B) {
    __shared__ float red[256];
    float s = 0.0f;
    for (int b = threadIdx.x; b < B; b += 256) s += g_anorm[b];
    red[threadIdx.x] = s;
    __syncthreads();
    #pragma unroll
    for (int o = 128; o > 0; o >>= 1) {
        if (threadIdx.x < o) red[threadIdx.x] += red[threadIdx.x + o];
        __syncthreads();
    }
    if (threadIdx.x == 0) g_Z = red[0];
}

// ---- K5: fused MLP: x -> y = x + ssp(ssp(x)@W1^T)@W2^T -> out = ssp(y)@Wo^T
// One block = 128 rows. 256 threads, 8x8 microtile. Activations transposed
// in smem (tsT[f][n], pitch 132). Weights staged raw per stage.
#define SMEM_FLOATS (2 * 128 * PITCH + 128 * 128)
#define SMEM_BYTES  (SMEM_FLOATS * 4)

__device__ __forceinline__ void gemm128(const float* __restrict__ Ws,
                                        const float* __restrict__ tsT,
                                        int fbase, int nbase, float acc[8][8]) {
    #pragma unroll 2
    for (int g = 0; g < 128; g += 4) {
        float a[8][4];
        #pragma unroll
        for (int i = 0; i < 8; i++) {
            float4 t = *(const float4*)(Ws + (fbase + i) * 128 + g);
            a[i][0] = t.x; a[i][1] = t.y; a[i][2] = t.z; a[i][3] = t.w;
        }
        #pragma unroll
        for (int gg = 0; gg < 4; gg++) {
            float4 b0 = *(const float4*)(tsT + (g + gg) * PITCH + nbase);
            float4 b1 = *(const float4*)(tsT + (g + gg) * PITCH + nbase + 4);
            float bb[8] = {b0.x, b0.y, b0.z, b0.w, b1.x, b1.y, b1.z, b1.w};
            #pragma unroll
            for (int i = 0; i < 8; i++)
                #pragma unroll
                for (int j = 0; j < 8; j++)
                    acc[i][j] = fmaf(a[i][gg], bb[j], acc[i][j]);
        }
    }
}

__device__ __forceinline__ void stage_w(const float* __restrict__ W, float* Ws, int tid) {
    const float4* src = (const float4*)W;
    float4* dst = (float4*)Ws;
    #pragma unroll
    for (int it = 0; it < 16; it++) dst[tid + it * 256] = __ldg(&src[tid + it * 256]);
}

__global__ void __launch_bounds__(256)
k_mlp(const int* __restrict__ idx,
      const float* __restrict__ W1, const float* __restrict__ W2,
      const float* __restrict__ Wo, float* __restrict__ out, int N) {
    extern __shared__ float sm[];
    float* tsT = sm;                    // [128][PITCH] current activation^T
    float* xsT = sm + 128 * PITCH;      // [128][PITCH] residual x^T
    float* Ws  = sm + 2 * 128 * PITCH;  // [128][128]   staged weight

    const int tid  = threadIdx.x;
    const int row0 = blockIdx.x * 128;
    const float zeps = EPSV * g_Z;

    // fill x^T and ssp(x)^T
    {
        const int nl = tid & 127, h = tid >> 7;
        const int n  = row0 + nl;
        float c = 0.0f;
        const float4* v4 = (const float4*)g_vm;
        if (n < N) {
            int b = __ldg(&idx[n]);
            c = g_w[n] / (g_anorm[b] + zeps);
            v4 = (const float4*)(g_vm + (size_t)b * 128);
        }
        #pragma unroll
        for (int q = 0; q < 16; q++) {
            int g4 = (h << 4) + q;
            float4 v = __ldg(&v4[g4]);
            int g = g4 * 4;
            float x0 = c * v.x, x1 = c * v.y, x2 = c * v.z, x3 = c * v.w;
            xsT[(g + 0) * PITCH + nl] = x0;  tsT[(g + 0) * PITCH + nl] = sspf(x0);
            xsT[(g + 1) * PITCH + nl] = x1;  tsT[(g + 1) * PITCH + nl] = sspf(x1);
            xsT[(g + 2) * PITCH + nl] = x2;  tsT[(g + 2) * PITCH + nl] = sspf(x2);
            xsT[(g + 3) * PITCH + nl] = x3;  tsT[(g + 3) * PITCH + nl] = sspf(x3);
        }
    }

    const int ty = tid >> 4, tx = tid & 15;
    const int fbase = ty * 8, nbase = tx * 8;
    float acc[8][8];

    // stage 1: t = ssp( ssp(x) @ W1^T )
    __syncthreads();
    stage_w(W1, Ws, tid);
    __syncthreads();
    #pragma unroll
    for (int i = 0; i < 8; i++)
        #pragma unroll
        for (int j = 0; j < 8; j++) acc[i][j] = 0.0f;
    gemm128(Ws, tsT, fbase, nbase, acc);
    __syncthreads();
    #pragma unroll
    for (int i = 0; i < 8; i++)
        #pragma unroll
        for (int j = 0; j < 8; j++)
            tsT[(fbase + i) * PITCH + nbase + j] = sspf(acc[i][j]);

    // stage 2: t = ssp( x + t @ W2^T )
    __syncthreads();
    stage_w(W2, Ws, tid);
    __syncthreads();
    #pragma unroll
    for (int i = 0; i < 8; i++)
        #pragma unroll
        for (int j = 0; j < 8; j++) acc[i][j] = 0.0f;
    gemm128(Ws, tsT, fbase, nbase, acc);
    __syncthreads();
    #pragma unroll
    for (int i = 0; i < 8; i++)
        #pragma unroll
        for (int j = 0; j < 8; j++)
            tsT[(fbase + i) * PITCH + nbase + j] =
                sspf(acc[i][j] + xsT[(fbase + i) * PITCH + nbase + j]);

    // stage 3: out = t @ Wo^T
    __syncthreads();
    stage_w(Wo, Ws, tid);
    __syncthreads();
    #pragma unroll
    for (int i = 0; i < 8; i++)
        #pragma unroll
        for (int j = 0; j < 8; j++) acc[i][j] = 0.0f;
    gemm128(Ws, tsT, fbase, nbase, acc);

    // store: acc[i][j] = out^T[fbase+i][nbase+j] -> out[(row0+nbase+j)*128 + fbase+i]
    #pragma unroll
    for (int j = 0; j < 8; j++) {
        int n = row0 + nbase + j;
        if (n < N) {
            float4 v0, v1;
            v0.x = acc[0][j]; v0.y = acc[1][j]; v0.z = acc[2][j]; v0.w = acc[3][j];
            v1.x = acc[4][j]; v1.y = acc[5][j]; v1.z = acc[6][j]; v1.w = acc[7][j];
            *(float4*)(out + (size_t)n * 128 + fbase)     = v0;
            *(float4*)(out + (size_t)n * 128 + fbase + 4) = v1;
        }
    }
}

extern "C" void kernel_launch(void* const* d_in, const int* in_sizes, int n_in,
                              void* d_out, int out_size) {
    const float* X   = (const float*)d_in[0];
    const float* ef  = (const float*)d_in[1];
    const int*   idx = (const int*)  d_in[2];
    const float* Wq  = (const float*)d_in[3];
    const float* bq  = (const float*)d_in[4];
    const float* Wk  = (const float*)d_in[5];
    const float* Wv  = (const float*)d_in[6];
    const float* W1  = (const float*)d_in[7];
    const float* W2  = (const float*)d_in[8];
    const float* Wo  = (const float*)d_in[9];
    float* out = (float*)d_out;

    const int N = in_sizes[0] / F_DIM;
    const int B = in_sizes[1];

    cudaFuncSetAttribute(k_mlp, cudaFuncAttributeMaxDynamicSharedMemorySize, SMEM_BYTES);

    k_prep<<<B, 128>>>(ef, Wk, Wv, Wq, bq);
    k_w<<<(N + 7) / 8, 256>>>(X, idx, N);
    k_exp<<<(N + 255) / 256, 256>>>(N);
    k_anorm<<<(B + 7) / 8, 256>>>(idx, N, B);
    k_Z<<<1, 256>>>(B);
    k_mlp<<<(N + 127) / 128, 256, SMEM_BYTES>>>(idx, W1, W2, Wo, out, N);
}

// round 16
// speedup vs baseline: 1.0512x; 1.0512x over previous
#include <cuda_runtime.h>
#include <cstdint>

#define F_DIM 128
#define PITCH 132
#define EPSV  1e-8f
#define LN2   0.6931471805599453f
#define RSQRT_F 0.08838834764831844f

#define N_CAP 524288
#define B_CAP 16384

__device__ float g_u [(size_t)B_CAP * F_DIM];
__device__ float g_vm[(size_t)B_CAP * F_DIM];
__device__ float g_d [B_CAP];
__device__ float g_anorm[B_CAP];
__device__ float g_w [N_CAP];
__device__ float g_max;
__device__ float g_Z;

__device__ __forceinline__ float sspf(float x) {
    float ax = fabsf(x);
    float l  = __logf(1.0f + __expf(-ax));
    return fmaxf(x, 0.0f) + (l - LN2);
}

__device__ __forceinline__ void atomicMaxFloat(float* addr, float v) {
    int* ai = (int*)addr;
    int cur = *ai;
    while (__int_as_float(cur) < v) {
        int prev = atomicCAS(ai, cur, __float_as_int(v));
        if (prev == cur) break;
        cur = prev;
    }
}

// ---- packed f32x2 helpers (FFMA2 — not emitted by ptxas from C++) ----
__device__ __forceinline__ uint64_t pack2(float x) {
    uint64_t r;
    asm("mov.b64 %0, {%1, %1};" : "=l"(r) : "f"(x));
    return r;
}
__device__ __forceinline__ void fma2(uint64_t& c, uint64_t a, uint64_t b) {
    asm("fma.rn.f32x2 %0, %1, %2, %0;" : "+l"(c) : "l"(a), "l"(b));
}
__device__ __forceinline__ float2 unpack2(uint64_t v) {
    float2 r;
    asm("mov.b64 {%0, %1}, %2;" : "=f"(r.x), "=f"(r.y) : "l"(v));
    return r;
}

// ---- K0: per-molecule precompute: u = (Wq^T km)/sqrt(F), vm, d = km.bq/sqrt(F)
__global__ void k_prep(const float* __restrict__ ef, const float* __restrict__ Wk,
                       const float* __restrict__ Wv, const float* __restrict__ Wq,
                       const float* __restrict__ bq) {
    __shared__ float kms[128];
    __shared__ float red[128];
    const int b = blockIdx.x;
    const int f = threadIdx.x;
    if (b == 0 && f == 0) g_max = -1e30f;

    float e  = ef[b];
    float e0 = fmaxf(e, 0.0f), e1 = fmaxf(-e, 0.0f);
    float k0 = e0 / fmaxf(e0, 1.0f);
    float k1 = e1 / fmaxf(e1, 1.0f);
    float km = k0 * Wk[2 * f] + k1 * Wk[2 * f + 1];
    g_vm[(size_t)b * 128 + f] = e0 * Wv[2 * f] + e1 * Wv[2 * f + 1];
    kms[f] = km;
    red[f] = km * bq[f];
    __syncthreads();
    #pragma unroll
    for (int s = 64; s > 0; s >>= 1) {
        if (f < s) red[f] += red[f + s];
        __syncthreads();
    }
    if (f == 0) g_d[b] = red[0] * RSQRT_F;

    float acc = 0.0f;
    #pragma unroll 8
    for (int ff = 0; ff < 128; ff++)
        acc = fmaf(kms[ff], __ldg(&Wq[ff * 128 + f]), acc);
    g_u[(size_t)b * 128 + f] = acc * RSQRT_F;
}

// ---- K1: w[n] = u[idx].x_n + d[idx]; block max -> atomic max. 1 warp/atom.
__global__ void k_w(const float* __restrict__ X, const int* __restrict__ idx, int N) {
    __shared__ float smax[8];
    const int warp = threadIdx.x >> 5;
    const int lane = threadIdx.x & 31;
    const int row  = blockIdx.x * 8 + warp;
    float wv = -1e30f;
    if (row < N) {
        int b = __ldg(&idx[row]);
        float4 x = __ldg(&((const float4*)X)[(size_t)row * 32 + lane]);
        float4 u = ((const float4*)g_u)[(size_t)b * 32 + lane];
        float s = x.x * u.x + x.y * u.y + x.z * u.z + x.w * u.w;
        #pragma unroll
        for (int o = 16; o > 0; o >>= 1) s += __shfl_down_sync(0xffffffffu, s, o);
        if (lane == 0) {
            s += g_d[b];
            g_w[row] = s;
            wv = s;
        }
    }
    if (lane == 0) smax[warp] = wv;
    __syncthreads();
    if (threadIdx.x == 0) {
        float m = smax[0];
        #pragma unroll
        for (int i = 1; i < 8; i++) m = fmaxf(m, smax[i]);
        atomicMaxFloat(&g_max, m);
    }
}

// ---- K2: p = exp(w - max)
__global__ void k_exp(int N) {
    int n = blockIdx.x * blockDim.x + threadIdx.x;
    if (n < N) g_w[n] = expf(g_w[n] - g_max);
}

// ---- K3: deterministic per-molecule sums (binary search on sorted idx)
__global__ void k_anorm(const int* __restrict__ idx, int N, int B) {
    const int b = blockIdx.x * 8 + (threadIdx.x >> 5);
    const int lane = threadIdx.x & 31;
    if (b >= B) return;
    int lo = 0, hi = N;
    while (lo < hi) { int m = (lo + hi) >> 1; if (idx[m] < b) lo = m + 1; else hi = m; }
    const int s0 = lo;
    hi = N;
    while (lo < hi) { int m = (lo + hi) >> 1; if (idx[m] < b + 1) lo = m + 1; else hi = m; }
    const int e0 = lo;
    float sum = 0.0f;
    for (int n = s0 + lane; n < e0; n += 32) sum += g_w[n];
    #pragma unroll
    for (int o = 16; o > 0; o >>= 1) sum += __shfl_down_sync(0xffffffffu, sum, o);
    if (lane == 0) g_anorm[b] = sum;
}

// ---- K4: Z = sum anorm (single block, fixed order)
__global__ void k_Z(int B) {
    __shared__ float red[256];
    float s = 0.0f;
    for (int b = threadIdx.x; b < B; b += 256) s += g_anorm[b];
    red[threadIdx.x] = s;
    __syncthreads();
    #pragma unroll
    for (int o = 128; o > 0; o >>= 1) {
        if (threadIdx.x < o) red[threadIdx.x] += red[threadIdx.x + o];
        __syncthreads();
    }
    if (threadIdx.x == 0) g_Z = red[0];
}

// ---- K5: fused MLP with packed f32x2 FFMA2 microkernel.
// One block = 128 rows. 256 threads, 8x8 microtile (acc as 8x4 f32x2 pairs
// along n). b-operands are contiguous in tsT -> loaded directly as 64-bit
// pairs (free); a-operand lane-duplicated via mov.b64 {a,a} (alu pipe).
#define SMEM_FLOATS (2 * 128 * PITCH + 128 * 128)
#define SMEM_BYTES  (SMEM_FLOATS * 4)

__device__ __forceinline__ void gemm128x2(const float* __restrict__ Ws,
                                          const float* __restrict__ tsT,
                                          int fbase, int nbase, uint64_t acc2[8][4]) {
    #pragma unroll 2
    for (int g = 0; g < 128; g += 4) {
        float a[8][4];
        #pragma unroll
        for (int i = 0; i < 8; i++) {
            float4 t = *(const float4*)(Ws + (fbase + i) * 128 + g);
            a[i][0] = t.x; a[i][1] = t.y; a[i][2] = t.z; a[i][3] = t.w;
        }
        #pragma unroll
        for (int gg = 0; gg < 4; gg++) {
            const ulonglong2* bp = (const ulonglong2*)(tsT + (g + gg) * PITCH + nbase);
            ulonglong2 bA = bp[0];
            ulonglong2 bB = bp[1];
            #pragma unroll
            for (int i = 0; i < 8; i++) {
                uint64_t ap = pack2(a[i][gg]);
                fma2(acc2[i][0], ap, bA.x);
                fma2(acc2[i][1], ap, bA.y);
                fma2(acc2[i][2], ap, bB.x);
                fma2(acc2[i][3], ap, bB.y);
            }
        }
    }
}

__device__ __forceinline__ void stage_w(const float* __restrict__ W, float* Ws, int tid) {
    const float4* src = (const float4*)W;
    float4* dst = (float4*)Ws;
    #pragma unroll
    for (int it = 0; it < 16; it++) dst[tid + it * 256] = __ldg(&src[tid + it * 256]);
}

__global__ void __launch_bounds__(256)
k_mlp(const int* __restrict__ idx,
      const float* __restrict__ W1, const float* __restrict__ W2,
      const float* __restrict__ Wo, float* __restrict__ out, int N) {
    extern __shared__ float sm[];
    float* tsT = sm;                    // [128][PITCH] current activation^T
    float* xsT = sm + 128 * PITCH;      // [128][PITCH] residual x^T
    float* Ws  = sm + 2 * 128 * PITCH;  // [128][128]   staged weight

    const int tid  = threadIdx.x;
    const int row0 = blockIdx.x * 128;
    const float zeps = EPSV * g_Z;

    // fill x^T and ssp(x)^T
    {
        const int nl = tid & 127, h = tid >> 7;
        const int n  = row0 + nl;
        float c = 0.0f;
        const float4* v4 = (const float4*)g_vm;
        if (n < N) {
            int b = __ldg(&idx[n]);
            c = g_w[n] / (g_anorm[b] + zeps);
            v4 = (const float4*)(g_vm + (size_t)b * 128);
        }
        #pragma unroll
        for (int q = 0; q < 16; q++) {
            int g4 = (h << 4) + q;
            float4 v = __ldg(&v4[g4]);
            int g = g4 * 4;
            float x0 = c * v.x, x1 = c * v.y, x2 = c * v.z, x3 = c * v.w;
            xsT[(g + 0) * PITCH + nl] = x0;  tsT[(g + 0) * PITCH + nl] = sspf(x0);
            xsT[(g + 1) * PITCH + nl] = x1;  tsT[(g + 1) * PITCH + nl] = sspf(x1);
            xsT[(g + 2) * PITCH + nl] = x2;  tsT[(g + 2) * PITCH + nl] = sspf(x2);
            xsT[(g + 3) * PITCH + nl] = x3;  tsT[(g + 3) * PITCH + nl] = sspf(x3);
        }
    }

    const int ty = tid >> 4, tx = tid & 15;
    const int fbase = ty * 8, nbase = tx * 8;
    uint64_t acc2[8][4];

    // stage 1: t = ssp( ssp(x) @ W1^T )
    __syncthreads();
    stage_w(W1, Ws, tid);
    __syncthreads();
    #pragma unroll
    for (int i = 0; i < 8; i++)
        #pragma unroll
        for (int j = 0; j < 4; j++) acc2[i][j] = 0ull;
    gemm128x2(Ws, tsT, fbase, nbase, acc2);
    __syncthreads();
    #pragma unroll
    for (int i = 0; i < 8; i++) {
        float2 p0 = unpack2(acc2[i][0]);
        float2 p1 = unpack2(acc2[i][1]);
        float2 p2 = unpack2(acc2[i][2]);
        float2 p3 = unpack2(acc2[i][3]);
        float4 v0, v1;
        v0.x = sspf(p0.x); v0.y = sspf(p0.y); v0.z = sspf(p1.x); v0.w = sspf(p1.y);
        v1.x = sspf(p2.x); v1.y = sspf(p2.y); v1.z = sspf(p3.x); v1.w = sspf(p3.y);
        *(float4*)(tsT + (fbase + i) * PITCH + nbase)     = v0;
        *(float4*)(tsT + (fbase + i) * PITCH + nbase + 4) = v1;
    }

    // stage 2: t = ssp( x + t @ W2^T )
    __syncthreads();
    stage_w(W2, Ws, tid);
    __syncthreads();
    #pragma unroll
    for (int i = 0; i < 8; i++)
        #pragma unroll
        for (int j = 0; j < 4; j++) acc2[i][j] = 0ull;
    gemm128x2(Ws, tsT, fbase, nbase, acc2);
    __syncthreads();
    #pragma unroll
    for (int i = 0; i < 8; i++) {
        const float* xr = xsT + (fbase + i) * PITCH + nbase;
        float2 p0 = unpack2(acc2[i][0]);
        float2 p1 = unpack2(acc2[i][1]);
        float2 p2 = unpack2(acc2[i][2]);
        float2 p3 = unpack2(acc2[i][3]);
        float4 v0, v1;
        v0.x = sspf(p0.x + xr[0]); v0.y = sspf(p0.y + xr[1]);
        v0.z = sspf(p1.x + xr[2]); v0.w = sspf(p1.y + xr[3]);
        v1.x = sspf(p2.x + xr[4]); v1.y = sspf(p2.y + xr[5]);
        v1.z = sspf(p3.x + xr[6]); v1.w = sspf(p3.y + xr[7]);
        *(float4*)(tsT + (fbase + i) * PITCH + nbase)     = v0;
        *(float4*)(tsT + (fbase + i) * PITCH + nbase + 4) = v1;
    }

    // stage 3: out = t @ Wo^T
    __syncthreads();
    stage_w(Wo, Ws, tid);
    __syncthreads();
    #pragma unroll
    for (int i = 0; i < 8; i++)
        #pragma unroll
        for (int j = 0; j < 4; j++) acc2[i][j] = 0ull;
    gemm128x2(Ws, tsT, fbase, nbase, acc2);

    // store: acc pair (i, jpair) = out^T[fbase+i][nbase+2jp .. +1]
    // -> out[(row0+nbase+j)*128 + fbase+i]
    {
        float c[8][8];
        #pragma unroll
        for (int i = 0; i < 8; i++) {
            float2 p0 = unpack2(acc2[i][0]);
            float2 p1 = unpack2(acc2[i][1]);
            float2 p2 = unpack2(acc2[i][2]);
            float2 p3 = unpack2(acc2[i][3]);
            c[i][0] = p0.x; c[i][1] = p0.y; c[i][2] = p1.x; c[i][3] = p1.y;
            c[i][4] = p2.x; c[i][5] = p2.y; c[i][6] = p3.x; c[i][7] = p3.y;
        }
        #pragma unroll
        for (int j = 0; j < 8; j++) {
            int n = row0 + nbase + j;
            if (n < N) {
                float4 v0, v1;
                v0.x = c[0][j]; v0.y = c[1][j]; v0.z = c[2][j]; v0.w = c[3][j];
                v1.x = c[4][j]; v1.y = c[5][j]; v1.z = c[6][j]; v1.w = c[7][j];
                *(float4*)(out + (size_t)n * 128 + fbase)     = v0;
                *(float4*)(out + (size_t)n * 128 + fbase + 4) = v1;
            }
        }
    }
}

extern "C" void kernel_launch(void* const* d_in, const int* in_sizes, int n_in,
                              void* d_out, int out_size) {
    const float* X   = (const float*)d_in[0];
    const float* ef  = (const float*)d_in[1];
    const int*   idx = (const int*)  d_in[2];
    const float* Wq  = (const float*)d_in[3];
    const float* bq  = (const float*)d_in[4];
    const float* Wk  = (const float*)d_in[5];
    const float* Wv  = (const float*)d_in[6];
    const float* W1  = (const float*)d_in[7];
    const float* W2  = (const float*)d_in[8];
    const float* Wo  = (const float*)d_in[9];
    float* out = (float*)d_out;

    const int N = in_sizes[0] / F_DIM;
    const int B = in_sizes[1];

    cudaFuncSetAttribute(k_mlp, cudaFuncAttributeMaxDynamicSharedMemorySize, SMEM_BYTES);

    k_prep<<<B, 128>>>(ef, Wk, Wv, Wq, bq);
    k_w<<<(N + 7) / 8, 256>>>(X, idx, N);
    k_exp<<<(N + 255) / 256, 256>>>(N);
    k_anorm<<<(B + 7) / 8, 256>>>(idx, N, B);
    k_Z<<<1, 256>>>(B);
    k_mlp<<<(N + 127) / 128, 256, SMEM_BYTES>>>(idx, W1, W2, Wo, out, N);
}